// round 6
// baseline (speedup 1.0000x reference)
#include <cuda_runtime.h>
#include <cuda_bf16.h>

#define NUM_DOCS   1000000
#define VOCAB      30522
#define NNZ        64000000
#define TOTAL4     (NNZ / 4)
#define Q_NNZ      32
#define SHARDS     4
#define TOP_K      100
#define RPS        250000
#define BUFCAP     20480
#define K2_THREADS 512
#define SLOTS      (BUFCAP / K2_THREADS)
#define SELCAP     256
#define GATHER_THREADS 512
#define GATHER_BLOCKS  (SHARDS * BUFCAP / GATHER_THREADS)   // 160
#define HASH_MUL   2654435761u

#define NCTAS      148
#define SEG        ((TOTAL4 + NCTAS - 1) / NCTAS)   // 108109 int4 per CTA
#define TILE_INT4  2048                              // 32 KB tiles
#define TILE_BYTES (TILE_INT4 * 16)
#define DEPTH      4                                 // pipeline stages
#define HTAB       512                               // hash-table slots (4 KB)
#define EMPTY64    0xFFFFFFFF00000000ull

// smem layout (dynamic)
#define SM_MBAR    0
#define SM_TAB     128
#define SM_TILE    (128 + HTAB * 8)                  // 4224
#define SM_TOTAL   (SM_TILE + DEPTH * TILE_BYTES)    // 135296

// ---- device scratch (zero-init at load; kernels restore invariant per replay) --
__device__ float g_scores[NUM_DOCS];
__device__ int   g_cand[SHARDS * BUFCAP];
__device__ float g_cscore[SHARDS * BUFCAP];
__device__ int   g_cnt[SHARDS];
__device__ float g_top_s[SHARDS * TOP_K];
__device__ int   g_top_i[SHARDS * TOP_K];
__device__ int   g_done;

// ---------------- async-copy / mbarrier helpers --------------------------------
__device__ __forceinline__ void mbar_init(unsigned a, int cnt) {
    asm volatile("mbarrier.init.shared.b64 [%0], %1;" :: "r"(a), "r"(cnt) : "memory");
}
__device__ __forceinline__ void mbar_expect_tx(unsigned a, int bytes) {
    asm volatile("mbarrier.arrive.expect_tx.shared.b64 _, [%0], %1;"
                 :: "r"(a), "r"(bytes) : "memory");
}
__device__ __forceinline__ void bulk_g2s(unsigned dst, const void* src, int bytes,
                                         unsigned mbar) {
    asm volatile(
        "cp.async.bulk.shared::cta.global.mbarrier::complete_tx::bytes [%0], [%1], %2, [%3];"
        :: "r"(dst), "l"(src), "r"(bytes), "r"(mbar) : "memory");
}
__device__ __forceinline__ void mbar_wait(unsigned a, int parity) {
    asm volatile(
        "{\n\t.reg .pred P;\n"
        "W%=:\n\t"
        "mbarrier.try_wait.parity.acquire.cta.shared::cta.b64 P, [%0], %1, 0x989680;\n\t"
        "@P bra D%=;\n\t"
        "bra W%=;\n"
        "D%=:\n\t}"
        :: "r"(a), "r"(parity) : "memory");
}

// ---------------- K1: cp.async.bulk pipeline + bloom + 4KB hash table -----------
__global__ void __launch_bounds__(1024, 1) score_kernel(
    const float* __restrict__ dv,
    const int*   __restrict__ di,
    const float* __restrict__ qv,
    const int*   __restrict__ qi)
{
    extern __shared__ char smem[];
    const unsigned smem_base = (unsigned)__cvta_generic_to_shared(smem);
    unsigned long long* tab = (unsigned long long*)(smem + SM_TAB);
    const int tid = threadIdx.x;

    // init pipeline mbarriers, publish to async proxy
    if (tid == 0) {
        #pragma unroll
        for (int s = 0; s < DEPTH; s++) mbar_init(smem_base + SM_MBAR + 8 * s, 1);
    }
    asm volatile("fence.proxy.async.shared::cta;" ::: "memory");
    __syncthreads();

    const int ctaStart   = blockIdx.x * SEG;
    const int ctaEnd     = min(ctaStart + SEG, TOTAL4);
    const int nInt4Total = ctaEnd - ctaStart;
    const int ntiles     = (nInt4Total + TILE_INT4 - 1) / TILE_INT4;

    // prologue: launch DEPTH bulk copies immediately (overlaps table build)
    if (tid == 0) {
        int np = min(DEPTH, ntiles);
        for (int t = 0; t < np; t++) {
            int start = t * TILE_INT4;
            int nb = min(TILE_INT4, nInt4Total - start) * 16;
            unsigned mb = smem_base + SM_MBAR + 8 * t;
            mbar_expect_tx(mb, nb);
            bulk_g2s(smem_base + SM_TILE + t * TILE_BYTES,
                     di + (size_t)(ctaStart + start) * 4, nb, mb);
        }
    }

    // build exact (idx -> coalesced value) hash table in 4KB smem
    for (int i = tid; i < HTAB; i += 1024) tab[i] = EMPTY64;
    __syncthreads();
    if (tid < Q_NNZ) {
        unsigned key = (unsigned)qi[tid];
        float val = qv[tid];
        unsigned h = (key * HASH_MUL) >> 23;  h &= (HTAB - 1);
        unsigned long long des = ((unsigned long long)key << 32)
                               | (unsigned long long)__float_as_uint(val);
        while (true) {
            unsigned long long old = atomicCAS(&tab[h], EMPTY64, des);
            if (old == EMPTY64) break;
            if ((unsigned)(old >> 32) == key) {        // duplicate term: coalesce
                atomicAdd((float*)&tab[h], val);       // low 4 bytes = value
                break;
            }
            h = (h + 1) & (HTAB - 1);
        }
    }
    // 64-bit register bloom over the 32 query terms
    unsigned long long bloom = 0ull;
    #pragma unroll
    for (int t = 0; t < Q_NNZ; t++)
        bloom |= 1ull << (((unsigned)__ldg(&qi[t]) * HASH_MUL) >> 26);
    __syncthreads();

    // main pipeline loop
    for (int t = 0; t < ntiles; t++) {
        int st  = t & (DEPTH - 1);
        int par = (t / DEPTH) & 1;
        unsigned mb = smem_base + SM_MBAR + 8 * st;
        mbar_wait(mb, par);

        const int4* tile = (const int4*)(smem + SM_TILE + st * TILE_BYTES);
        int tileStart = t * TILE_INT4;
        int nInt4 = min(TILE_INT4, nInt4Total - tileStart);

        #pragma unroll
        for (int r = 0; r < 2; r++) {
            int slot = tid + r * 1024;
            if (slot < nInt4) {
                int4 v = tile[slot];                         // conflict-free LDS.128
                int ebase = (ctaStart + tileStart + slot) << 2;
                int idxs[4] = {v.x, v.y, v.z, v.w};
                #pragma unroll
                for (int j = 0; j < 4; j++) {
                    unsigned idx = (unsigned)idxs[j];
                    if ((bloom >> ((idx * HASH_MUL) >> 26)) & 1ull) {   // ~0.4% pass
                        unsigned h = (idx * HASH_MUL) >> 23;  h &= (HTAB - 1);
                        float qq = 0.0f;
                        while (true) {                         // ~1.07 probes avg
                            unsigned long long e = tab[h];
                            unsigned k = (unsigned)(e >> 32);
                            if (k == idx) { qq = __uint_as_float((unsigned)e); break; }
                            if (k == 0xFFFFFFFFu) break;
                            h = (h + 1) & (HTAB - 1);
                        }
                        if (qq != 0.0f) {                      // true hit (~0.1%)
                            int elem = ebase + j;
                            float contrib = __ldg(&dv[elem]) * qq;
                            int doc = elem >> 6;
                            float old = atomicAdd(&g_scores[doc], contrib);
                            if (old == 0.0f) {                 // exactly-once append
                                int sh = doc / RPS;
                                int p = atomicAdd(&g_cnt[sh], 1);
                                if (p < BUFCAP) g_cand[sh * BUFCAP + p] = doc;
                            }
                        }
                    }
                }
            }
        }
        __syncthreads();   // all lanes done with this stage's buffer

        int tn = t + DEPTH;
        if (tid == 0 && tn < ntiles) {
            int start = tn * TILE_INT4;
            int nb = min(TILE_INT4, nInt4Total - start) * 16;
            mbar_expect_tx(mb, nb);
            bulk_g2s(smem_base + SM_TILE + st * TILE_BYTES,
                     di + (size_t)(ctaStart + start) * 4, nb, mb);
        }
    }
}

// ---------------- K2a: full-chip scatter -> coalesced gather --------------------
__global__ void __launch_bounds__(GATHER_THREADS) gather_kernel() {
    int i = blockIdx.x * GATHER_THREADS + threadIdx.x;
    int s = i / BUFCAP;
    int j = i - s * BUFCAP;
    int n = g_cnt[s]; if (n > BUFCAP) n = BUFCAP;
    float sc = 0.0f;
    if (j < n) {
        int doc = g_cand[i];
        sc = g_scores[doc];
        g_scores[doc] = 0.0f;    // restore replay invariant
    }
    g_cscore[i] = sc;            // coalesced; pads 0
}

// ---------------- K2b: per-shard top-100 (register cache) + fused merge ---------
__device__ __forceinline__ int block_count(int local, int* red) {
    int w = __reduce_add_sync(0xFFFFFFFFu, local);
    int warp = threadIdx.x >> 5;
    int lane = threadIdx.x & 31;
    if (lane == 0) red[warp] = w;
    __syncthreads();
    if (threadIdx.x == 0) {
        int t = 0;
        #pragma unroll
        for (int i = 0; i < K2_THREADS / 32; i++) t += red[i];
        red[32] = t;
    }
    __syncthreads();
    int total = red[32];
    __syncthreads();
    return total;
}

__global__ void __launch_bounds__(K2_THREADS) topk_merge_kernel(float* __restrict__ out) {
    __shared__ int red[33];
    __shared__ unsigned long long s_sel[SELCAP];
    __shared__ int s_num;
    __shared__ int s_last;

    const int s = blockIdx.x;
    const int tid = threadIdx.x;
    int n = g_cnt[s]; if (n > BUFCAP) n = BUFCAP;

    unsigned sx[SLOTS];
    #pragma unroll
    for (int k = 0; k < SLOTS; k++)
        sx[k] = __float_as_uint(g_cscore[s * BUFCAP + tid + k * K2_THREADS]);
    if (tid == 0) s_num = 0;
    __syncthreads();

    unsigned thr;
    if (n >= TOP_K) {
        unsigned lo = 0u, hi = 0x7F800000u;
        while (hi - lo > 1u) {
            unsigned mid = lo + ((hi - lo) >> 1);
            int local = 0;
            #pragma unroll
            for (int k = 0; k < SLOTS; k++) local += (sx[k] >= mid) ? 1 : 0;
            int c = block_count(local, red);
            if (c >= TOP_K) lo = mid; else hi = mid;
        }
        thr = (lo == 0u) ? 1u : lo;
    } else {
        thr = 1u;
    }

    #pragma unroll
    for (int k = 0; k < SLOTS; k++) {
        if (sx[k] >= thr) {
            int i = tid + k * K2_THREADS;
            int doc = g_cand[s * BUFCAP + i];
            int p = atomicAdd(&s_num, 1);
            if (p < SELCAP)
                s_sel[p] = ((unsigned long long)sx[k] << 32)
                         | (unsigned long long)(0xFFFFFFFFu - (unsigned)(doc - s * RPS));
        }
    }
    __syncthreads();
    int m = s_num; if (m > SELCAP) m = SELCAP;
    if (tid < m) {
        unsigned long long key = s_sel[tid];
        int rank = 0;
        for (int j = 0; j < m; j++) rank += (s_sel[j] > key) ? 1 : 0;
        if (rank < TOP_K) {
            g_top_s[s * TOP_K + rank] = __uint_as_float((unsigned)(key >> 32));
            g_top_i[s * TOP_K + rank] = s * RPS
                + (int)(0xFFFFFFFFu - (unsigned)(key & 0xFFFFFFFFull));
        }
    }
    if (tid >= m && tid < TOP_K) {       // degenerate pad (unreachable)
        g_top_s[s * TOP_K + tid] = 0.0f;
        g_top_i[s * TOP_K + tid] = s * RPS + tid;
    }
    if (tid == 0) g_cnt[s] = 0;

    __threadfence();
    __syncthreads();
    if (tid == 0) {
        int old = atomicAdd(&g_done, 1);
        s_last = (old == SHARDS - 1) ? 1 : 0;
    }
    __syncthreads();
    if (!s_last) return;
    __threadfence();

    __shared__ unsigned long long k400[SHARDS * TOP_K];
    __shared__ float sc400[SHARDS * TOP_K];
    __shared__ int   id400[SHARDS * TOP_K];
    for (int p = tid; p < SHARDS * TOP_K; p += K2_THREADS) {
        float sc = __ldcg(&g_top_s[p]);
        int   id = __ldcg(&g_top_i[p]);
        k400[p] = ((unsigned long long)__float_as_uint(sc) << 32)
                | (unsigned long long)(0xFFFFFFFFu - (unsigned)p);
        sc400[p] = sc;
        id400[p] = id;
    }
    __syncthreads();
    if (tid < SHARDS * TOP_K) {
        unsigned long long key = k400[tid];
        int rank = 0;
        #pragma unroll 4
        for (int j = 0; j < SHARDS * TOP_K; j++) rank += (k400[j] > key) ? 1 : 0;
        if (rank < TOP_K) {
            out[rank]         = sc400[tid];
            out[TOP_K + rank] = (float)id400[tid];
        }
    }
    if (tid == 0) g_done = 0;
}

// ---------------- launch --------------------------------------------------------
extern "C" void kernel_launch(void* const* d_in, const int* in_sizes, int n_in,
                              void* d_out, int out_size) {
    const float* dv = (const float*)d_in[0];   // doc_values   [NNZ]
    const float* qv = (const float*)d_in[1];   // q_values     [Q_NNZ]
    const int*   di = (const int*)  d_in[2];   // doc_indices  [NNZ]
    /* d_in[3] = row_ids: redundant, never read */
    const int*   qi = (const int*)  d_in[4];   // q_indices    [Q_NNZ]
    float* out = (float*)d_out;

    cudaFuncSetAttribute(score_kernel,
                         cudaFuncAttributeMaxDynamicSharedMemorySize, SM_TOTAL);

    score_kernel<<<NCTAS, 1024, SM_TOTAL>>>(dv, di, qv, qi);
    gather_kernel<<<GATHER_BLOCKS, GATHER_THREADS>>>();
    topk_merge_kernel<<<SHARDS, K2_THREADS>>>(out);
}

// round 7
// speedup vs baseline: 1.8351x; 1.8351x over previous
#include <cuda_runtime.h>
#include <cuda_bf16.h>

#define NUM_DOCS   1000000
#define VOCAB      30522
#define NNZ        64000000
#define TOTAL4     (NNZ / 4)
#define Q_NNZ      32
#define SHARDS     4
#define TOP_K      100
#define RPS        250000
#define BUFCAP     20480
#define K2_THREADS 512
#define SLOTS      (BUFCAP / K2_THREADS)
#define SELCAP     256
#define GATHER_THREADS 512
#define GATHER_BLOCKS  (SHARDS * BUFCAP / GATHER_THREADS)   // 160
#define HASH_MUL   2654435761u
#define HTAB       512
#define EMPTY_KEY  0xFFFFFFFFu
#define EMPTY64    0xFFFFFFFF00000000ull

#define K1_THREADS 512
#define K1_BPSM    3                       // 48 warps/SM (regs capped at 42)
#define K1_BLOCKS  (148 * K1_BPSM)         // 444

// ---- device scratch (zero-init at load; kernels restore invariant per replay) --
__device__ float g_scores[NUM_DOCS];
__device__ int   g_cand[SHARDS * BUFCAP];
__device__ float g_cscore[SHARDS * BUFCAP];
__device__ int   g_cnt[SHARDS];
__device__ float g_top_s[SHARDS * TOP_K];
__device__ int   g_top_i[SHARDS * TOP_K];
__device__ int   g_done;

// ---------------- K1: LDG streaming + register bloom + 4KB hash table -----------
__global__ void __launch_bounds__(K1_THREADS, K1_BPSM) score_kernel(
    const float* __restrict__ dv,
    const int*   __restrict__ di,
    const float* __restrict__ qv,
    const int*   __restrict__ qi)
{
    __shared__ unsigned long long tab[HTAB];   // 4 KB: (idx<<32 | value_bits)
    const int tid = threadIdx.x;

    for (int i = tid; i < HTAB; i += K1_THREADS) tab[i] = EMPTY64;
    __syncthreads();
    if (tid < Q_NNZ) {
        unsigned key = (unsigned)qi[tid];
        float val = qv[tid];
        unsigned h = ((key * HASH_MUL) >> 23) & (HTAB - 1);
        unsigned long long des = ((unsigned long long)key << 32)
                               | (unsigned long long)__float_as_uint(val);
        while (true) {
            unsigned long long old = atomicCAS(&tab[h], EMPTY64, des);
            if (old == EMPTY64) break;
            if ((unsigned)(old >> 32) == key) {      // duplicate term: coalesce sum
                atomicAdd((float*)&tab[h], val);     // low word = value
                break;
            }
            h = (h + 1) & (HTAB - 1);
        }
    }
    // 64-bit register bloom over the 32 query terms
    unsigned long long bloom = 0ull;
    #pragma unroll
    for (int t = 0; t < Q_NNZ; t++)
        bloom |= 1ull << (((unsigned)__ldg(&qi[t]) * HASH_MUL) >> 26);
    __syncthreads();

    const int4* di4 = (const int4*)di;
    const int stride = K1_BLOCKS * K1_THREADS;
    const int gid = blockIdx.x * K1_THREADS + tid;

    for (int c0 = gid; c0 < TOTAL4; c0 += stride * 4) {
        // front-batched loads (4 x LDG.128 in flight)
        int4 v[4];
        int cs[4];
        #pragma unroll
        for (int u = 0; u < 4; u++) {
            int c = c0 + u * stride;
            cs[u] = c;
            v[u] = (c < TOTAL4) ? __ldcs(&di4[c]) : make_int4(-1, -1, -1, -1);
        }
        #pragma unroll
        for (int u = 0; u < 4; u++) {
            int idxs[4] = {v[u].x, v[u].y, v[u].z, v[u].w};
            #pragma unroll
            for (int j = 0; j < 4; j++) {
                unsigned idx = (unsigned)idxs[j];
                // bloom gate: pads (0xFFFFFFFF) hash to some bit; table probe
                // then rejects them (key mismatch / empty), so no correctness
                // issue either way.
                if ((bloom >> ((idx * HASH_MUL) >> 26)) & 1ull) {   // ~39% pass
                    unsigned h = ((idx * HASH_MUL) >> 23) & (HTAB - 1);
                    float qq = 0.0f;
                    #pragma unroll 1
                    while (true) {                                  // ~1.07 probes
                        unsigned long long e = tab[h];
                        unsigned k = (unsigned)(e >> 32);
                        if (k == idx) { qq = __uint_as_float((unsigned)e); break; }
                        if (k == EMPTY_KEY) break;
                        h = (h + 1) & (HTAB - 1);
                    }
                    if (qq != 0.0f) {                               // true hit ~0.1%
                        int elem = (cs[u] << 2) + j;
                        float contrib = __ldg(&dv[elem]) * qq;
                        int doc = cs[u] >> 4;                       // 16 int4 / doc
                        float old = atomicAdd(&g_scores[doc], contrib);
                        if (old == 0.0f && contrib > 0.0f) {        // exactly-once
                            int sh = doc / RPS;
                            int p = atomicAdd(&g_cnt[sh], 1);
                            if (p < BUFCAP) g_cand[sh * BUFCAP + p] = doc;
                        }
                    }
                }
            }
        }
    }
}

// ---------------- K2a: full-chip scatter -> coalesced gather --------------------
__global__ void __launch_bounds__(GATHER_THREADS) gather_kernel() {
    int i = blockIdx.x * GATHER_THREADS + threadIdx.x;
    int s = i / BUFCAP;
    int j = i - s * BUFCAP;
    int n = g_cnt[s]; if (n > BUFCAP) n = BUFCAP;
    float sc = 0.0f;
    if (j < n) {
        int doc = g_cand[i];
        sc = g_scores[doc];
        g_scores[doc] = 0.0f;    // restore replay invariant
    }
    g_cscore[i] = sc;            // coalesced; pads 0
}

// ---------------- K2b: per-shard top-100 (register cache) + fused merge ---------
__device__ __forceinline__ int block_count(int local, int* red) {
    int w = __reduce_add_sync(0xFFFFFFFFu, local);
    int warp = threadIdx.x >> 5;
    int lane = threadIdx.x & 31;
    if (lane == 0) red[warp] = w;
    __syncthreads();
    if (threadIdx.x == 0) {
        int t = 0;
        #pragma unroll
        for (int i = 0; i < K2_THREADS / 32; i++) t += red[i];
        red[32] = t;
    }
    __syncthreads();
    int total = red[32];
    __syncthreads();
    return total;
}

__global__ void __launch_bounds__(K2_THREADS) topk_merge_kernel(float* __restrict__ out) {
    __shared__ int red[33];
    __shared__ unsigned long long s_sel[SELCAP];
    __shared__ int s_num;
    __shared__ int s_last;

    const int s = blockIdx.x;
    const int tid = threadIdx.x;
    int n = g_cnt[s]; if (n > BUFCAP) n = BUFCAP;

    unsigned sx[SLOTS];
    #pragma unroll
    for (int k = 0; k < SLOTS; k++)
        sx[k] = __float_as_uint(g_cscore[s * BUFCAP + tid + k * K2_THREADS]);
    if (tid == 0) s_num = 0;
    __syncthreads();

    unsigned thr;
    if (n >= TOP_K) {
        unsigned lo = 0u, hi = 0x7F800000u;
        while (hi - lo > 1u) {
            unsigned mid = lo + ((hi - lo) >> 1);
            int local = 0;
            #pragma unroll
            for (int k = 0; k < SLOTS; k++) local += (sx[k] >= mid) ? 1 : 0;
            int c = block_count(local, red);
            if (c >= TOP_K) lo = mid; else hi = mid;
        }
        thr = (lo == 0u) ? 1u : lo;
    } else {
        thr = 1u;
    }

    #pragma unroll
    for (int k = 0; k < SLOTS; k++) {
        if (sx[k] >= thr) {
            int i = tid + k * K2_THREADS;
            int doc = g_cand[s * BUFCAP + i];
            int p = atomicAdd(&s_num, 1);
            if (p < SELCAP)
                s_sel[p] = ((unsigned long long)sx[k] << 32)
                         | (unsigned long long)(0xFFFFFFFFu - (unsigned)(doc - s * RPS));
        }
    }
    __syncthreads();
    int m = s_num; if (m > SELCAP) m = SELCAP;
    if (tid < m) {
        unsigned long long key = s_sel[tid];
        int rank = 0;
        for (int j = 0; j < m; j++) rank += (s_sel[j] > key) ? 1 : 0;
        if (rank < TOP_K) {
            g_top_s[s * TOP_K + rank] = __uint_as_float((unsigned)(key >> 32));
            g_top_i[s * TOP_K + rank] = s * RPS
                + (int)(0xFFFFFFFFu - (unsigned)(key & 0xFFFFFFFFull));
        }
    }
    if (tid >= m && tid < TOP_K) {       // degenerate pad (unreachable)
        g_top_s[s * TOP_K + tid] = 0.0f;
        g_top_i[s * TOP_K + tid] = s * RPS + tid;
    }
    if (tid == 0) g_cnt[s] = 0;

    __threadfence();
    __syncthreads();
    if (tid == 0) {
        int old = atomicAdd(&g_done, 1);
        s_last = (old == SHARDS - 1) ? 1 : 0;
    }
    __syncthreads();
    if (!s_last) return;
    __threadfence();

    __shared__ unsigned long long k400[SHARDS * TOP_K];
    __shared__ float sc400[SHARDS * TOP_K];
    __shared__ int   id400[SHARDS * TOP_K];
    for (int p = tid; p < SHARDS * TOP_K; p += K2_THREADS) {
        float sc = __ldcg(&g_top_s[p]);
        int   id = __ldcg(&g_top_i[p]);
        k400[p] = ((unsigned long long)__float_as_uint(sc) << 32)
                | (unsigned long long)(0xFFFFFFFFu - (unsigned)p);
        sc400[p] = sc;
        id400[p] = id;
    }
    __syncthreads();
    if (tid < SHARDS * TOP_K) {
        unsigned long long key = k400[tid];
        int rank = 0;
        #pragma unroll 4
        for (int j = 0; j < SHARDS * TOP_K; j++) rank += (k400[j] > key) ? 1 : 0;
        if (rank < TOP_K) {
            out[rank]         = sc400[tid];
            out[TOP_K + rank] = (float)id400[tid];
        }
    }
    if (tid == 0) g_done = 0;
}

// ---------------- launch --------------------------------------------------------
extern "C" void kernel_launch(void* const* d_in, const int* in_sizes, int n_in,
                              void* d_out, int out_size) {
    const float* dv = (const float*)d_in[0];   // doc_values   [NNZ]
    const float* qv = (const float*)d_in[1];   // q_values     [Q_NNZ]
    const int*   di = (const int*)  d_in[2];   // doc_indices  [NNZ]
    /* d_in[3] = row_ids: redundant, never read */
    const int*   qi = (const int*)  d_in[4];   // q_indices    [Q_NNZ]
    float* out = (float*)d_out;

    score_kernel<<<K1_BLOCKS, K1_THREADS>>>(dv, di, qv, qi);
    gather_kernel<<<GATHER_BLOCKS, GATHER_THREADS>>>();
    topk_merge_kernel<<<SHARDS, K2_THREADS>>>(out);
}